// round 13
// baseline (speedup 1.0000x reference)
#include <cuda_runtime.h>
#include <cuda_bf16.h>
#include <stdint.h>

#define B 1024
#define D 768

// ---------------- scratch (device globals; no allocation allowed) ----------
__device__ __nv_bfloat16      g_img_bf[B * D];
__device__ __nv_bfloat16      g_txt_bf[B * D];
__device__ unsigned long long g_hash[B];
__device__ float2             g_part[B * 32];    // per (row, 32-col block): (max, sumexp)
__device__ float              g_loss[B];
__device__ int                g_cnt;             // phase arrival counter (reset at end)

// ---------------- small asm helpers (all base-arch features) ----------------
__device__ __forceinline__ uint32_t smem_to_u32(const void* smem_ptr) {
    uint32_t addr;
    asm("{ .reg .u64 tmp; cvta.to.shared.u64 tmp, %1; cvt.u32.u64 %0, tmp; }"
        : "=r"(addr) : "l"(smem_ptr));
    return addr;
}
#define CP_ASYNC16(smem_u32, gptr) \
    asm volatile("cp.async.cg.shared.global [%0], [%1], 16;" \
                 :: "r"(smem_u32), "l"(gptr) : "memory")
#define CP_COMMIT() asm volatile("cp.async.commit_group;" ::: "memory")
#define CP_WAIT(N)  asm volatile("cp.async.wait_group %0;" :: "n"(N) : "memory")

#define LDSM_X4(R0, R1, R2, R3, ADDR) \
    asm volatile("ldmatrix.sync.aligned.m8n8.x4.shared.b16 {%0,%1,%2,%3}, [%4];" \
                 : "=r"(R0), "=r"(R1), "=r"(R2), "=r"(R3) : "r"(ADDR))

__device__ __forceinline__ void mma16816(float* d, const uint32_t* a, const uint32_t* b) {
    asm volatile(
        "mma.sync.aligned.m16n8k16.row.col.f32.bf16.bf16.f32 "
        "{%0,%1,%2,%3}, {%4,%5,%6,%7}, {%8,%9}, {%0,%1,%2,%3};"
        : "+f"(d[0]), "+f"(d[1]), "+f"(d[2]), "+f"(d[3])
        : "r"(a[0]), "r"(a[1]), "r"(a[2]), "r"(a[3]), "r"(b[0]), "r"(b[1]));
}

// ---------------- fast exp on the FMA pipe (x <= 0) --------------------------
__device__ __forceinline__ float fexp(float x) {
    float y = fmaxf(x * 1.44269504088896340736f, -126.0f);
    float yi = floorf(y);
    float f = y - yi;
    float p = 1.8775767e-3f;
    p = fmaf(p, f, 8.9893397e-3f);
    p = fmaf(p, f, 5.5826318e-2f);
    p = fmaf(p, f, 2.4015361e-1f);
    p = fmaf(p, f, 6.9315308e-1f);
    p = fmaf(p, f, 1.0f);
    float sc = __int_as_float(((int)yi + 127) << 23);
    return p * sc;
}

// ---------------- hashing ------------------------------------------------------
__device__ __forceinline__ unsigned long long splitmix64(unsigned long long x) {
    x += 0x9E3779B97F4A7C15ULL;
    x = (x ^ (x >> 30)) * 0xBF58476D1CE4E5B9ULL;
    x = (x ^ (x >> 27)) * 0x94D049BB133111EBULL;
    return x ^ (x >> 31);
}
__device__ __forceinline__ unsigned long long hmix(int k, float v) {
    return splitmix64(((unsigned long long)k << 32) ^ (unsigned long long)__float_as_uint(v));
}

// ---------------- GEMM geometry ------------------------------------------------
#define BM 64
#define BN 64
#define BK 32
#define ROW_BYTES 80
#define TILE_SM   (64 * ROW_BYTES)
#define NKSTEP    (D / BK)
#define NPIPE     3
#define SMEM_BYTES (NPIPE * 2 * TILE_SM)   // 30720
#define NCTA      256
#define NTHR      256

// ---------------- grid sync ------------------------------------------------------
__device__ __forceinline__ void grid_sync(int target) {
    __threadfence();
    __syncthreads();
    if (threadIdx.x == 0) {
        atomicAdd(&g_cnt, 1);
        while (atomicAdd(&g_cnt, 0) < target) { __nanosleep(32); }
    }
    __syncthreads();
}

// ================================================================================
__global__ __launch_bounds__(NTHR)
void fused_kernel(const float* __restrict__ img, const float* __restrict__ txt,
                  const float* __restrict__ scale_p, float* __restrict__ out) {
    __shared__ __align__(16) char sm[SMEM_BYTES];

    const int tid  = threadIdx.x;
    const int wid  = tid >> 5;
    const int lane = tid & 31;
    const int bx   = blockIdx.x;

    // ---------------- phase 0: fp32->bf16 convert + per-row img hash -----------
    // 2048 warps: warps with (wid<4) handle img row (convert+hash),
    //             warps with (wid>=4) handle txt row (convert only).
    {
        const int row   = bx * 4 + (wid & 3);
        const int isTxt = wid >> 2;
        const float4* src = reinterpret_cast<const float4*>((isTxt ? txt : img) + (size_t)row * D);
        uint2* dst = reinterpret_cast<uint2*>((isTxt ? g_txt_bf : g_img_bf) + (size_t)row * D);
        unsigned long long h = 0ULL;
        #pragma unroll
        for (int q = 0; q < 6; q++) {
            const int idx = lane + q * 32;
            float4 a = src[idx];
            __nv_bfloat162 a01 = __float22bfloat162_rn(make_float2(a.x, a.y));
            __nv_bfloat162 a23 = __float22bfloat162_rn(make_float2(a.z, a.w));
            dst[idx] = make_uint2(*reinterpret_cast<uint32_t*>(&a01),
                                  *reinterpret_cast<uint32_t*>(&a23));
            if (!isTxt) {
                const int k = idx * 4;
                h += hmix(k, a.x) + hmix(k + 1, a.y) + hmix(k + 2, a.z) + hmix(k + 3, a.w);
            }
        }
        if (!isTxt) {
            #pragma unroll
            for (int off = 16; off > 0; off >>= 1) h += __shfl_down_sync(0xffffffffu, h, off);
            if (lane == 0) g_hash[row] = h;
        }
    }

    grid_sync(NCTA);          // all bf16 + hashes visible

    // ---------------- phase 1: mma.sync bf16 GEMM + online-softmax epilogue ----
    // CTA 64x64, 8 warps in 4(m) x 2(n), warp tile 16x32.
    {
        const int mBase = (bx >> 4) * BM;
        const int nBase = (bx & 15) * BN;
        const int wm = (wid >> 1) * 16;
        const int wn = (wid & 1) * 32;

        const uint32_t smem_base = smem_to_u32(sm);
        const char* imgB = (const char*)g_img_bf;
        const char* txtB = (const char*)g_txt_bf;

        auto load_stage = [&](int s, int kt) {
            #pragma unroll
            for (int i = 0; i < 2; i++) {
                const int c   = tid + i * 256;     // 0..511
                const int ab  = c >> 8;
                const int l   = c & 255;
                const int row = l >> 2;
                const int seg = (l & 3) * 16;
                const char* gp = (ab ? txtB + ((size_t)(nBase + row) * D + kt) * 2
                                     : imgB + ((size_t)(mBase + row) * D + kt) * 2) + seg;
                uint32_t sp = smem_base + s * (2 * TILE_SM) + ab * TILE_SM + row * ROW_BYTES + seg;
                CP_ASYNC16(sp, gp);
            }
            CP_COMMIT();
        };

        const int aRow   = lane & 15;
        const int aChunk = (lane >> 4) * 16;
        const int bRow   = ((lane >> 4) & 1) * 8 + (lane & 7);
        const int bChunk = ((lane >> 3) & 1) * 16;

        float acc[4][4];
        #pragma unroll
        for (int ni = 0; ni < 4; ni++)
            #pragma unroll
            for (int q = 0; q < 4; q++) acc[ni][q] = 0.0f;

        load_stage(0, 0);
        load_stage(1, BK);

        for (int ks = 0; ks < NKSTEP; ks++) {
            const int buf = ks % NPIPE;
            if (ks + 2 < NKSTEP) { load_stage((ks + 2) % NPIPE, (ks + 2) * BK); CP_WAIT(2); }
            else if (ks + 1 < NKSTEP) { CP_WAIT(1); }
            else { CP_WAIT(0); }
            __syncthreads();

            const uint32_t aBase = smem_base + buf * (2 * TILE_SM);
            const uint32_t bBase = aBase + TILE_SM;

            #pragma unroll
            for (int h = 0; h < 2; h++) {
                const int kb = h * 32;
                uint32_t a[4], b[4][2];
                LDSM_X4(a[0], a[1], a[2], a[3],
                        aBase + (wm + aRow) * ROW_BYTES + kb + aChunk);
                LDSM_X4(b[0][0], b[0][1], b[1][0], b[1][1],
                        bBase + (wn + 0 + bRow) * ROW_BYTES + kb + bChunk);
                LDSM_X4(b[2][0], b[2][1], b[3][0], b[3][1],
                        bBase + (wn + 16 + bRow) * ROW_BYTES + kb + bChunk);
                #pragma unroll
                for (int ni = 0; ni < 4; ni++)
                    mma16816(acc[ni], a, b[ni]);
            }
            __syncthreads();
        }

        // online-softmax epilogue: warp covers rows wm+g, wm+g+8 over one 32-col block
        const float s = *scale_p;
        const int t = lane & 3;
        const int g = lane >> 2;
        const int cb = (nBase + wn) >> 5;
        float v0[8], v1[8];
        #pragma unroll
        for (int ni = 0; ni < 4; ni++) {
            v0[ni * 2 + 0] = acc[ni][0] * s;
            v0[ni * 2 + 1] = acc[ni][1] * s;
            v1[ni * 2 + 0] = acc[ni][2] * s;
            v1[ni * 2 + 1] = acc[ni][3] * s;
        }
        float m0 = v0[0], m1 = v1[0];
        #pragma unroll
        for (int q = 1; q < 8; q++) { m0 = fmaxf(m0, v0[q]); m1 = fmaxf(m1, v1[q]); }
        m0 = fmaxf(m0, __shfl_xor_sync(0xffffffffu, m0, 1));
        m0 = fmaxf(m0, __shfl_xor_sync(0xffffffffu, m0, 2));
        m1 = fmaxf(m1, __shfl_xor_sync(0xffffffffu, m1, 1));
        m1 = fmaxf(m1, __shfl_xor_sync(0xffffffffu, m1, 2));
        float s0 = 0.0f, s1 = 0.0f;
        #pragma unroll
        for (int q = 0; q < 8; q++) { s0 += fexp(v0[q] - m0); s1 += fexp(v1[q] - m1); }
        s0 += __shfl_xor_sync(0xffffffffu, s0, 1);
        s0 += __shfl_xor_sync(0xffffffffu, s0, 2);
        s1 += __shfl_xor_sync(0xffffffffu, s1, 1);
        s1 += __shfl_xor_sync(0xffffffffu, s1, 2);
        if (t == 0) {
            const int row0 = mBase + wm + g;
            g_part[row0 * 32 + cb]       = make_float2(m0, s0);
            g_part[(row0 + 8) * 32 + cb] = make_float2(m1, s1);
        }
    }

    grid_sync(2 * NCTA);      // all partials visible

    // ---------------- phase 2: combine (1 row per warp, warps 0-3) --------------
    {
        unsigned long long* sm_hash = reinterpret_cast<unsigned long long*>(sm);
        #pragma unroll
        for (int r = 0; r < 4; r++) sm_hash[tid + r * 256] = g_hash[tid + r * 256];
        __syncthreads();

        if (wid < 4) {
            const int j = bx * 4 + wid;

            float2 p = g_part[j * 32 + lane];
            float m = p.x;
            #pragma unroll
            for (int off = 16; off > 0; off >>= 1)
                m = fmaxf(m, __shfl_xor_sync(0xffffffffu, m, off));
            float s = p.y * fexp(p.x - m);
            #pragma unroll
            for (int off = 16; off > 0; off >>= 1)
                s += __shfl_xor_sync(0xffffffffu, s, off);

            // label: first i < j with identical img row (smem hash prefilter + verify)
            const unsigned long long hj = sm_hash[j];
            int label = j;
            int lastRejected = -1;
            while (true) {
                int mymin = 0x7fffffff;
                for (int i = lane; i < j; i += 32) {
                    if (sm_hash[i] == hj && i > lastRejected) { mymin = i; break; }
                }
                #pragma unroll
                for (int off = 16; off > 0; off >>= 1)
                    mymin = min(mymin, __shfl_xor_sync(0xffffffffu, mymin, off));
                if (mymin == 0x7fffffff) break;
                bool eq = true;
                #pragma unroll
                for (int q = 0; q < 6; q++) {
                    const int k4 = lane + q * 32;
                    float4 a  = reinterpret_cast<const float4*>(img + (size_t)mymin * D)[k4];
                    float4 bb = reinterpret_cast<const float4*>(img + (size_t)j * D)[k4];
                    bool e = (a.x == bb.x) && (a.y == bb.y) && (a.z == bb.z) && (a.w == bb.w);
                    if (!__all_sync(0xffffffffu, e)) { eq = false; break; }
                }
                if (eq) { label = mymin; break; }
                lastRejected = mymin;
            }

            // needed logit: scale * dot(img_bf[j], txt_bf[label])
            const uint4* ia = reinterpret_cast<const uint4*>(g_img_bf + (size_t)j * D);
            const uint4* tb = reinterpret_cast<const uint4*>(g_txt_bf + (size_t)label * D);
            float dot = 0.0f;
            #pragma unroll
            for (int q = 0; q < 3; q++) {
                uint4 av = ia[lane + q * 32];
                uint4 bv = tb[lane + q * 32];
                const uint32_t au[4] = {av.x, av.y, av.z, av.w};
                const uint32_t bu[4] = {bv.x, bv.y, bv.z, bv.w};
                #pragma unroll
                for (int r = 0; r < 4; r++) {
                    float2 af = __bfloat1622float2(*reinterpret_cast<const __nv_bfloat162*>(&au[r]));
                    float2 bf = __bfloat1622float2(*reinterpret_cast<const __nv_bfloat162*>(&bu[r]));
                    dot = fmaf(af.x, bf.x, dot);
                    dot = fmaf(af.y, bf.y, dot);
                }
            }
            #pragma unroll
            for (int off = 16; off > 0; off >>= 1)
                dot += __shfl_xor_sync(0xffffffffu, dot, off);

            if (lane == 0) g_loss[j] = m + logf(s) - (*scale_p) * dot;
        }
    }

    // ---------------- phase 3: last-arriving CTA -> deterministic mean ----------
    __threadfence();
    __syncthreads();
    __shared__ int s_last;
    if (tid == 0) s_last = (atomicAdd(&g_cnt, 1) == 3 * NCTA - 1) ? 1 : 0;
    __syncthreads();
    if (s_last) {
        float acc = 0.0f;
        #pragma unroll
        for (int r = 0; r < 4; r++) acc += g_loss[tid + r * 256];
        float* red = reinterpret_cast<float*>(sm);
        red[tid] = acc;
        __syncthreads();
        for (int w = 128; w > 0; w >>= 1) {
            if (tid < w) red[tid] += red[tid + w];
            __syncthreads();
        }
        if (tid == 0) {
            out[0] = red[0] * (1.0f / (float)B);
            g_cnt = 0;   // reset for next graph replay
        }
    }
}

// ---------------- entry -----------------------------------------------------------
extern "C" void kernel_launch(void* const* d_in, const int* in_sizes, int n_in,
                              void* d_out, int out_size) {
    const float* img   = (const float*)d_in[0];
    const float* txt   = (const float*)d_in[1];
    const float* scale = (const float*)d_in[2];
    float* out = (float*)d_out;

    fused_kernel<<<NCTA, NTHR>>>(img, txt, scale, out);
}

// round 14
// speedup vs baseline: 1.0193x; 1.0193x over previous
#include <cuda_runtime.h>
#include <cuda_bf16.h>
#include <stdint.h>

#define B 1024
#define D 768

// ---------------- scratch (device globals; no allocation allowed) ----------
__device__ __nv_bfloat16      g_img_bf[B * D];
__device__ __nv_bfloat16      g_txt_bf[B * D];
__device__ unsigned long long g_hash[B];
__device__ float2             g_part[B * 32];    // per (row, 32-col block): (max, sumexp)
__device__ float              g_loss[B];
__device__ int                g_cnt;             // phase arrival counter (reset at end)

// ---------------- small asm helpers (all base-arch features) ----------------
__device__ __forceinline__ uint32_t smem_to_u32(const void* smem_ptr) {
    uint32_t addr;
    asm("{ .reg .u64 tmp; cvta.to.shared.u64 tmp, %1; cvt.u32.u64 %0, tmp; }"
        : "=r"(addr) : "l"(smem_ptr));
    return addr;
}
#define CP_ASYNC16(smem_u32, gptr) \
    asm volatile("cp.async.cg.shared.global [%0], [%1], 16;" \
                 :: "r"(smem_u32), "l"(gptr) : "memory")
#define CP_COMMIT() asm volatile("cp.async.commit_group;" ::: "memory")
#define CP_WAIT(N)  asm volatile("cp.async.wait_group %0;" :: "n"(N) : "memory")

#define LDSM_X4(R0, R1, R2, R3, ADDR) \
    asm volatile("ldmatrix.sync.aligned.m8n8.x4.shared.b16 {%0,%1,%2,%3}, [%4];" \
                 : "=r"(R0), "=r"(R1), "=r"(R2), "=r"(R3) : "r"(ADDR))

__device__ __forceinline__ void mma16816(float* d, const uint32_t* a, const uint32_t* b) {
    asm volatile(
        "mma.sync.aligned.m16n8k16.row.col.f32.bf16.bf16.f32 "
        "{%0,%1,%2,%3}, {%4,%5,%6,%7}, {%8,%9}, {%0,%1,%2,%3};"
        : "+f"(d[0]), "+f"(d[1]), "+f"(d[2]), "+f"(d[3])
        : "r"(a[0]), "r"(a[1]), "r"(a[2]), "r"(a[3]), "r"(b[0]), "r"(b[1]));
}

// ---------------- fast exp on the FMA pipe (x <= 0) --------------------------
__device__ __forceinline__ float fexp(float x) {
    float y = fmaxf(x * 1.44269504088896340736f, -126.0f);
    float yi = floorf(y);
    float f = y - yi;
    float p = 1.8775767e-3f;
    p = fmaf(p, f, 8.9893397e-3f);
    p = fmaf(p, f, 5.5826318e-2f);
    p = fmaf(p, f, 2.4015361e-1f);
    p = fmaf(p, f, 6.9315308e-1f);
    p = fmaf(p, f, 1.0f);
    float sc = __int_as_float(((int)yi + 127) << 23);
    return p * sc;
}

// ---------------- hashing ------------------------------------------------------
__device__ __forceinline__ unsigned long long splitmix64(unsigned long long x) {
    x += 0x9E3779B97F4A7C15ULL;
    x = (x ^ (x >> 30)) * 0xBF58476D1CE4E5B9ULL;
    x = (x ^ (x >> 27)) * 0x94D049BB133111EBULL;
    return x ^ (x >> 31);
}
__device__ __forceinline__ unsigned long long hmix(int k, float v) {
    return splitmix64(((unsigned long long)k << 32) ^ (unsigned long long)__float_as_uint(v));
}

// ---------------- GEMM geometry ------------------------------------------------
#define BM 64
#define BN 64
#define BK 32
#define ROW_BYTES 80
#define TILE_SM   (64 * ROW_BYTES)
#define NKSTEP    (D / BK)
#define NPIPE     3
#define SMEM_BYTES (NPIPE * 2 * TILE_SM)   // 30720
#define NCTA      256
#define NTHR      256

// ---------------- grid sync ------------------------------------------------------
__device__ __forceinline__ void grid_sync(int target) {
    __threadfence();
    __syncthreads();
    if (threadIdx.x == 0) {
        atomicAdd(&g_cnt, 1);
        while (atomicAdd(&g_cnt, 0) < target) { __nanosleep(32); }
    }
    __syncthreads();
}

// ================================================================================
__global__ __launch_bounds__(NTHR)
void fused_kernel(const float* __restrict__ img, const float* __restrict__ txt,
                  const float* __restrict__ scale_p, float* __restrict__ out) {
    __shared__ __align__(16) char sm[SMEM_BYTES];

    const int tid  = threadIdx.x;
    const int wid  = tid >> 5;
    const int lane = tid & 31;
    const int bx   = blockIdx.x;

    // ---------------- phase 0: fp32->bf16 convert + per-row img hash -----------
    // 2048 warps: warps with (wid<4) handle img row (convert+hash),
    //             warps with (wid>=4) handle txt row (convert only).
    {
        const int row   = bx * 4 + (wid & 3);
        const int isTxt = wid >> 2;
        const float4* src = reinterpret_cast<const float4*>((isTxt ? txt : img) + (size_t)row * D);
        uint2* dst = reinterpret_cast<uint2*>((isTxt ? g_txt_bf : g_img_bf) + (size_t)row * D);
        unsigned long long h = 0ULL;
        #pragma unroll
        for (int q = 0; q < 6; q++) {
            const int idx = lane + q * 32;
            float4 a = src[idx];
            __nv_bfloat162 a01 = __float22bfloat162_rn(make_float2(a.x, a.y));
            __nv_bfloat162 a23 = __float22bfloat162_rn(make_float2(a.z, a.w));
            dst[idx] = make_uint2(*reinterpret_cast<uint32_t*>(&a01),
                                  *reinterpret_cast<uint32_t*>(&a23));
            if (!isTxt) {
                const int k = idx * 4;
                h += hmix(k, a.x) + hmix(k + 1, a.y) + hmix(k + 2, a.z) + hmix(k + 3, a.w);
            }
        }
        if (!isTxt) {
            #pragma unroll
            for (int off = 16; off > 0; off >>= 1) h += __shfl_down_sync(0xffffffffu, h, off);
            if (lane == 0) g_hash[row] = h;
        }
    }

    grid_sync(NCTA);          // all bf16 + hashes visible

    // ---------------- phase 1: mma.sync bf16 GEMM + online-softmax epilogue ----
    // CTA 64x64, 8 warps in 4(m) x 2(n), warp tile 16x32.
    {
        const int mBase = (bx >> 4) * BM;
        const int nBase = (bx & 15) * BN;
        const int wm = (wid >> 1) * 16;
        const int wn = (wid & 1) * 32;

        const uint32_t smem_base = smem_to_u32(sm);
        const char* imgB = (const char*)g_img_bf;
        const char* txtB = (const char*)g_txt_bf;

        auto load_stage = [&](int s, int kt) {
            #pragma unroll
            for (int i = 0; i < 2; i++) {
                const int c   = tid + i * 256;     // 0..511
                const int ab  = c >> 8;
                const int l   = c & 255;
                const int row = l >> 2;
                const int seg = (l & 3) * 16;
                const char* gp = (ab ? txtB + ((size_t)(nBase + row) * D + kt) * 2
                                     : imgB + ((size_t)(mBase + row) * D + kt) * 2) + seg;
                uint32_t sp = smem_base + s * (2 * TILE_SM) + ab * TILE_SM + row * ROW_BYTES + seg;
                CP_ASYNC16(sp, gp);
            }
            CP_COMMIT();
        };

        const int aRow   = lane & 15;
        const int aChunk = (lane >> 4) * 16;
        const int bRow   = ((lane >> 4) & 1) * 8 + (lane & 7);
        const int bChunk = ((lane >> 3) & 1) * 16;

        float acc[4][4];
        #pragma unroll
        for (int ni = 0; ni < 4; ni++)
            #pragma unroll
            for (int q = 0; q < 4; q++) acc[ni][q] = 0.0f;

        load_stage(0, 0);
        load_stage(1, BK);

        for (int ks = 0; ks < NKSTEP; ks++) {
            const int buf = ks % NPIPE;
            if (ks + 2 < NKSTEP) { load_stage((ks + 2) % NPIPE, (ks + 2) * BK); CP_WAIT(2); }
            else if (ks + 1 < NKSTEP) { CP_WAIT(1); }
            else { CP_WAIT(0); }
            __syncthreads();

            const uint32_t aBase = smem_base + buf * (2 * TILE_SM);
            const uint32_t bBase = aBase + TILE_SM;

            #pragma unroll
            for (int h = 0; h < 2; h++) {
                const int kb = h * 32;
                uint32_t a[4], b[4][2];
                LDSM_X4(a[0], a[1], a[2], a[3],
                        aBase + (wm + aRow) * ROW_BYTES + kb + aChunk);
                LDSM_X4(b[0][0], b[0][1], b[1][0], b[1][1],
                        bBase + (wn + 0 + bRow) * ROW_BYTES + kb + bChunk);
                LDSM_X4(b[2][0], b[2][1], b[3][0], b[3][1],
                        bBase + (wn + 16 + bRow) * ROW_BYTES + kb + bChunk);
                #pragma unroll
                for (int ni = 0; ni < 4; ni++)
                    mma16816(acc[ni], a, b[ni]);
            }
            __syncthreads();
        }

        // online-softmax epilogue: warp covers rows wm+g, wm+g+8 over one 32-col block
        const float s = *scale_p;
        const int t = lane & 3;
        const int g = lane >> 2;
        const int cb = (nBase + wn) >> 5;
        float v0[8], v1[8];
        #pragma unroll
        for (int ni = 0; ni < 4; ni++) {
            v0[ni * 2 + 0] = acc[ni][0] * s;
            v0[ni * 2 + 1] = acc[ni][1] * s;
            v1[ni * 2 + 0] = acc[ni][2] * s;
            v1[ni * 2 + 1] = acc[ni][3] * s;
        }
        float m0 = v0[0], m1 = v1[0];
        #pragma unroll
        for (int q = 1; q < 8; q++) { m0 = fmaxf(m0, v0[q]); m1 = fmaxf(m1, v1[q]); }
        m0 = fmaxf(m0, __shfl_xor_sync(0xffffffffu, m0, 1));
        m0 = fmaxf(m0, __shfl_xor_sync(0xffffffffu, m0, 2));
        m1 = fmaxf(m1, __shfl_xor_sync(0xffffffffu, m1, 1));
        m1 = fmaxf(m1, __shfl_xor_sync(0xffffffffu, m1, 2));
        float s0 = 0.0f, s1 = 0.0f;
        #pragma unroll
        for (int q = 0; q < 8; q++) { s0 += fexp(v0[q] - m0); s1 += fexp(v1[q] - m1); }
        s0 += __shfl_xor_sync(0xffffffffu, s0, 1);
        s0 += __shfl_xor_sync(0xffffffffu, s0, 2);
        s1 += __shfl_xor_sync(0xffffffffu, s1, 1);
        s1 += __shfl_xor_sync(0xffffffffu, s1, 2);
        if (t == 0) {
            const int row0 = mBase + wm + g;
            g_part[row0 * 32 + cb]       = make_float2(m0, s0);
            g_part[(row0 + 8) * 32 + cb] = make_float2(m1, s1);
        }
    }

    grid_sync(2 * NCTA);      // all partials visible

    // ---------------- phase 2: combine (1 row per warp, warps 0-3) --------------
    {
        unsigned long long* sm_hash = reinterpret_cast<unsigned long long*>(sm);
        #pragma unroll
        for (int r = 0; r < 4; r++) sm_hash[tid + r * 256] = g_hash[tid + r * 256];
        __syncthreads();

        if (wid < 4) {
            const int j = bx * 4 + wid;

            float2 p = g_part[j * 32 + lane];
            float m = p.x;
            #pragma unroll
            for (int off = 16; off > 0; off >>= 1)
                m = fmaxf(m, __shfl_xor_sync(0xffffffffu, m, off));
            float s = p.y * fexp(p.x - m);
            #pragma unroll
            for (int off = 16; off > 0; off >>= 1)
                s += __shfl_xor_sync(0xffffffffu, s, off);

            // label: first i < j with identical img row (smem hash prefilter + verify)
            const unsigned long long hj = sm_hash[j];
            int label = j;
            int lastRejected = -1;
            while (true) {
                int mymin = 0x7fffffff;
                for (int i = lane; i < j; i += 32) {
                    if (sm_hash[i] == hj && i > lastRejected) { mymin = i; break; }
                }
                #pragma unroll
                for (int off = 16; off > 0; off >>= 1)
                    mymin = min(mymin, __shfl_xor_sync(0xffffffffu, mymin, off));
                if (mymin == 0x7fffffff) break;
                bool eq = true;
                #pragma unroll
                for (int q = 0; q < 6; q++) {
                    const int k4 = lane + q * 32;
                    float4 a  = reinterpret_cast<const float4*>(img + (size_t)mymin * D)[k4];
                    float4 bb = reinterpret_cast<const float4*>(img + (size_t)j * D)[k4];
                    bool e = (a.x == bb.x) && (a.y == bb.y) && (a.z == bb.z) && (a.w == bb.w);
                    if (!__all_sync(0xffffffffu, e)) { eq = false; break; }
                }
                if (eq) { label = mymin; break; }
                lastRejected = mymin;
            }

            // needed logit: scale * dot(img_bf[j], txt_bf[label])
            const uint4* ia = reinterpret_cast<const uint4*>(g_img_bf + (size_t)j * D);
            const uint4* tb = reinterpret_cast<const uint4*>(g_txt_bf + (size_t)label * D);
            float dot = 0.0f;
            #pragma unroll
            for (int q = 0; q < 3; q++) {
                uint4 av = ia[lane + q * 32];
                uint4 bv = tb[lane + q * 32];
                const uint32_t au[4] = {av.x, av.y, av.z, av.w};
                const uint32_t bu[4] = {bv.x, bv.y, bv.z, bv.w};
                #pragma unroll
                for (int r = 0; r < 4; r++) {
                    float2 af = __bfloat1622float2(*reinterpret_cast<const __nv_bfloat162*>(&au[r]));
                    float2 bf = __bfloat1622float2(*reinterpret_cast<const __nv_bfloat162*>(&bu[r]));
                    dot = fmaf(af.x, bf.x, dot);
                    dot = fmaf(af.y, bf.y, dot);
                }
            }
            #pragma unroll
            for (int off = 16; off > 0; off >>= 1)
                dot += __shfl_xor_sync(0xffffffffu, dot, off);

            if (lane == 0) g_loss[j] = m + logf(s) - (*scale_p) * dot;
        }
    }

    // ---------------- phase 3: last-arriving CTA -> deterministic mean ----------
    __threadfence();
    __syncthreads();
    __shared__ int s_last;
    if (tid == 0) s_last = (atomicAdd(&g_cnt, 1) == 3 * NCTA - 1) ? 1 : 0;
    __syncthreads();
    if (s_last) {
        float acc = 0.0f;
        #pragma unroll
        for (int r = 0; r < 4; r++) acc += g_loss[tid + r * 256];
        float* red = reinterpret_cast<float*>(sm);
        red[tid] = acc;
        __syncthreads();
        for (int w = 128; w > 0; w >>= 1) {
            if (tid < w) red[tid] += red[tid + w];
            __syncthreads();
        }
        if (tid == 0) {
            out[0] = red[0] * (1.0f / (float)B);
            g_cnt = 0;   // reset for next graph replay
        }
    }
}

// ---------------- entry -----------------------------------------------------------
extern "C" void kernel_launch(void* const* d_in, const int* in_sizes, int n_in,
                              void* d_out, int out_size) {
    const float* img   = (const float*)d_in[0];
    const float* txt   = (const float*)d_in[1];
    const float* scale = (const float*)d_in[2];
    float* out = (float*)d_out;

    fused_kernel<<<NCTA, NTHR>>>(img, txt, scale, out);
}